// round 10
// baseline (speedup 1.0000x reference)
#include <cuda_runtime.h>
#include <cuda_fp16.h>
#include <math.h>
#include <stdint.h>

// Problem constants
#define Bb 4
#define Tt 2048
#define Cc 1024
#define Hh 16
#define HD 64
#define Mrows (Bb*Tt)   // 8192
#define GK 1024

// ---------------------------------------------------------------------------
// Helpers
// ---------------------------------------------------------------------------
__device__ __forceinline__ uint32_t smem_u32(const void* p) {
    uint32_t a;
    asm("{ .reg .u64 t; cvta.to.shared.u64 t, %1; cvt.u32.u64 %0, t; }"
        : "=r"(a) : "l"(p));
    return a;
}

__device__ __forceinline__ void cp_async16(uint32_t dst, const void* src) {
    asm volatile("cp.async.cg.shared.global [%0], [%1], 16;"
                 :: "r"(dst), "l"(src) : "memory");
}
#define CP_COMMIT() asm volatile("cp.async.commit_group;" ::: "memory")
#define CP_WAIT0()  asm volatile("cp.async.wait_group 0;" ::: "memory")
#define CP_WAIT1()  asm volatile("cp.async.wait_group 1;" ::: "memory")
#define CP_WAIT2()  asm volatile("cp.async.wait_group 2;" ::: "memory")

// mma.sync m16n8k16 fp16 inputs, fp32 accumulate
__device__ __forceinline__ void mma16n8k16(
    float* c, const uint32_t* a, const uint32_t* b)
{
    asm volatile(
        "mma.sync.aligned.m16n8k16.row.col.f32.f16.f16.f32 "
        "{%0,%1,%2,%3}, {%4,%5,%6,%7}, {%8,%9}, {%0,%1,%2,%3};"
        : "+f"(c[0]), "+f"(c[1]), "+f"(c[2]), "+f"(c[3])
        : "r"(a[0]), "r"(a[1]), "r"(a[2]), "r"(a[3]),
          "r"(b[0]), "r"(b[1]));
}

__device__ __forceinline__ void ldsm_x4(uint32_t* r, uint32_t addr) {
    asm volatile(
        "ldmatrix.sync.aligned.m8n8.x4.shared.b16 {%0,%1,%2,%3}, [%4];"
        : "=r"(r[0]), "=r"(r[1]), "=r"(r[2]), "=r"(r[3]) : "r"(addr));
}
__device__ __forceinline__ void ldsm_x4_t(uint32_t* r, uint32_t addr) {
    asm volatile(
        "ldmatrix.sync.aligned.m8n8.x4.trans.shared.b16 {%0,%1,%2,%3}, [%4];"
        : "=r"(r[0]), "=r"(r[1]), "=r"(r[2]), "=r"(r[3]) : "r"(addr));
}

__device__ __forceinline__ uint32_t pack_h2(float a, float b) {
    __half2 h = __floats2half2_rn(a, b);
    return *reinterpret_cast<uint32_t*>(&h);
}

// ---------------------------------------------------------------------------
// Scratch (allocation-free: __device__ globals)
// ---------------------------------------------------------------------------
__device__ __half g_hxq[(size_t)Mrows*Cc];
__device__ __half g_hxk[(size_t)Mrows*Cc];
__device__ __half g_hxv[(size_t)Mrows*Cc];
__device__ __half g_hWq[(size_t)Cc*Cc];
__device__ __half g_hWk[(size_t)Cc*Cc];
__device__ __half g_hWv[(size_t)Cc*Cc];
__device__ __half g_hWo[(size_t)Cc*Cc];
__device__ __half g_Q[(size_t)Bb*Hh*Tt*HD];
__device__ __half g_K[(size_t)Bb*Hh*Tt*HD];
__device__ __half g_V[(size_t)Bb*Hh*Tt*HD];
__device__ __half g_Y[(size_t)Bb*Tt*Cc];

// ---------------------------------------------------------------------------
// Batched fp32 -> fp16 convert, MLP=4 (four independent loads in flight)
// ---------------------------------------------------------------------------
struct CvtArgs {
    const float4* src[7];
    uint2*        dst[7];
    int           n4[7];
};

__global__ __launch_bounds__(256) void cvt_kernel(CvtArgs a) {
    int j = blockIdx.y;
    const float4* __restrict__ s = a.src[j];
    uint2* __restrict__ d = a.dst[j];
    int n4 = a.n4[j];
    int stride = gridDim.x * blockDim.x;
    int i = blockIdx.x * blockDim.x + threadIdx.x;
    for (; i + 3 * stride < n4; i += 4 * stride) {
        float4 v0 = s[i];
        float4 v1 = s[i + stride];
        float4 v2 = s[i + 2 * stride];
        float4 v3 = s[i + 3 * stride];
        uint2 o0, o1, o2, o3;
        o0.x = pack_h2(v0.x, v0.y); o0.y = pack_h2(v0.z, v0.w);
        o1.x = pack_h2(v1.x, v1.y); o1.y = pack_h2(v1.z, v1.w);
        o2.x = pack_h2(v2.x, v2.y); o2.y = pack_h2(v2.z, v2.w);
        o3.x = pack_h2(v3.x, v3.y); o3.y = pack_h2(v3.z, v3.w);
        d[i] = o0;
        d[i + stride] = o1;
        d[i + 2 * stride] = o2;
        d[i + 3 * stride] = o3;
    }
    for (; i < n4; i += stride) {
        float4 v = s[i];
        uint2 o;
        o.x = pack_h2(v.x, v.y);
        o.y = pack_h2(v.z, v.w);
        d[i] = o;
    }
}

// ---------------------------------------------------------------------------
// GEMM core: BM=128, BN=128, BK=64, 8 warps (2m x 4n), warp tile 64x32.
// 3-stage cp.async pipeline, single __syncthreads per K-iteration.
// ---------------------------------------------------------------------------
#define HROWB 144               // bytes per smem row (72 halves)
#define GTILE (128*HROWB)       // 18432 B
#define GSTAGE (2*GTILE)        // 36864 B (A tile + B tile)
#define GEMM_SMEM (3*GSTAGE)    // 110592 B
#define GKT (GK/64)             // 16

__device__ __forceinline__ void gemm_core(
    const __half* __restrict__ A, const __half* __restrict__ W,
    int bm, int bn, uint32_t sbase,
    int tid, int wm, int wn, int lane, float c[4][4][4])
{
#pragma unroll
    for (int i = 0; i < 4; i++)
#pragma unroll
        for (int j = 0; j < 4; j++)
#pragma unroll
            for (int r = 0; r < 4; r++) c[i][j][r] = 0.f;

    const int ch = tid & 7;
    const int rb = tid >> 3;
    const uint32_t lmrow = (uint32_t)(lane & 15) * HROWB + ((lane >> 4) << 4);

    auto issue_stage = [&](int stage, int k0) {
        uint32_t a_s = sbase + stage * GSTAGE;
        uint32_t b_s = a_s + GTILE;
#pragma unroll
        for (int i = 0; i < 4; i++) {
            int r = rb + i * 32;
            uint32_t so = (uint32_t)r * HROWB + ch * 16;
            cp_async16(a_s + so, A + (size_t)(bm + r) * GK + k0 + ch * 8);
            cp_async16(b_s + so, W + (size_t)(bn + r) * GK + k0 + ch * 8);
        }
        CP_COMMIT();
    };

    issue_stage(0, 0);
    issue_stage(1, 64);

    for (int it = 0; it < GKT; ++it) {
        // stage it resident: all but the most recent commit must be done
        if (it + 1 < GKT) CP_WAIT1(); else CP_WAIT0();
        __syncthreads();       // all warps done with the buffer being refilled
        int nx = it + 2;
        if (nx < GKT)
            issue_stage(nx % 3, nx * 64);   // overlaps MMA below

        uint32_t as_b = sbase + (it % 3) * GSTAGE;
        uint32_t bs_b = as_b + GTILE;

#pragma unroll
        for (int ks = 0; ks < 4; ks++) {
            uint32_t af[4][4], bf[2][4];
#pragma unroll
            for (int mt = 0; mt < 4; mt++)
                ldsm_x4(af[mt],
                        as_b + (uint32_t)(wm * 64 + mt * 16) * HROWB + lmrow + ks * 32);
#pragma unroll
            for (int pr = 0; pr < 2; pr++)
                ldsm_x4(bf[pr],
                        bs_b + (uint32_t)(wn * 32 + pr * 16) * HROWB + lmrow + ks * 32);
#pragma unroll
            for (int mt = 0; mt < 4; mt++)
#pragma unroll
                for (int nt = 0; nt < 4; nt++) {
                    uint32_t b2[2];
                    b2[0] = bf[nt >> 1][nt & 1];
                    b2[1] = bf[nt >> 1][(nt & 1) + 2];
                    mma16n8k16(c[mt][nt], af[mt], b2);
                }
        }
    }
}

// Merged Q/K/V projection
struct QKVArgs {
    const __half* A[3];
    const __half* W[3];
    __half*       out[3];
};

__global__ __launch_bounds__(256, 2) void qkv_gemm(QKVArgs args)
{
    extern __shared__ __align__(16) char dsm[];
    const int tid = threadIdx.x;
    const int wid = tid >> 5, lane = tid & 31;
    const int wm = wid & 1, wn = wid >> 1;
    const int bm = blockIdx.y * 128, bn = blockIdx.x * 128;
    const int g = blockIdx.z;
    const int lg = lane >> 2, lk = lane & 3;

    float c[4][4][4];
    gemm_core(args.A[g], args.W[g], bm, bn, smem_u32(dsm),
              tid, wm, wn, lane, c);

    __half* out = args.out[g];
#pragma unroll
    for (int mt = 0; mt < 4; mt++) {
        int r0 = bm + wm * 64 + mt * 16 + lg;
#pragma unroll
        for (int nt = 0; nt < 4; nt++) {
            int n = bn + wn * 32 + nt * 8 + lk * 2;
            int h = n >> 6, d = n & 63;
            int b0 = r0 >> 11, t0 = r0 & (Tt - 1);
            *(__half2*)(out + ((size_t)(b0 * Hh + h) * Tt + t0) * HD + d) =
                __floats2half2_rn(c[mt][nt][0], c[mt][nt][1]);
            int r1 = r0 + 8;
            int b1 = r1 >> 11, t1 = r1 & (Tt - 1);
            *(__half2*)(out + ((size_t)(b1 * Hh + h) * Tt + t1) * HD + d) =
                __floats2half2_rn(c[mt][nt][2], c[mt][nt][3]);
        }
    }
}

// O-projection: fp32 out + bias
__global__ __launch_bounds__(256, 2) void oproj_gemm(
    const __half* __restrict__ A, const __half* __restrict__ W,
    const float* __restrict__ bias, float* __restrict__ out)
{
    extern __shared__ __align__(16) char dsm[];
    const int tid = threadIdx.x;
    const int wid = tid >> 5, lane = tid & 31;
    const int wm = wid & 1, wn = wid >> 1;
    const int bm = blockIdx.y * 128, bn = blockIdx.x * 128;
    const int lg = lane >> 2, lk = lane & 3;

    float c[4][4][4];
    gemm_core(A, W, bm, bn, smem_u32(dsm), tid, wm, wn, lane, c);

#pragma unroll
    for (int mt = 0; mt < 4; mt++) {
        int r0 = bm + wm * 64 + mt * 16 + lg;
#pragma unroll
        for (int nt = 0; nt < 4; nt++) {
            int n = bn + wn * 32 + nt * 8 + lk * 2;
            float2 bv = *(const float2*)(bias + n);
            *(float2*)(out + (size_t)r0 * Cc + n) =
                make_float2(c[mt][nt][0] + bv.x, c[mt][nt][1] + bv.y);
            *(float2*)(out + (size_t)(r0 + 8) * Cc + n) =
                make_float2(c[mt][nt][2] + bv.x, c[mt][nt][3] + bv.y);
        }
    }
}

// ---------------------------------------------------------------------------
// fp16 tensor-core causal flash attention (validated R9, unchanged)
// ---------------------------------------------------------------------------
#define FT_BYTES (64*HROWB)       // 9216 B
#define FA_SMEM (5*FT_BYTES)      // 46080 B (Q staged in 5th tile)

__global__ __launch_bounds__(128) void flash_mma(
    const __half* __restrict__ Qg, const __half* __restrict__ Kg,
    const __half* __restrict__ Vg, __half* __restrict__ Yg)
{
    extern __shared__ __align__(16) char fsm[];
    const uint32_t sb = smem_u32(fsm);
    const uint32_t ps_b = sb + 4 * FT_BYTES;

    const int tid = threadIdx.x;
    const int w = tid >> 5, lane = tid & 31;
    const int lg = lane >> 2, lk = lane & 3;
    const int qb = blockIdx.x;
    const int bh = blockIdx.y;

    const __half* Qbase = Qg + ((size_t)bh * Tt + qb * 64) * HD;
    const __half* Kbase = Kg + (size_t)bh * Tt * HD;
    const __half* Vbase = Vg + (size_t)bh * Tt * HD;

    const int lrow0 = w * 16 + lg;
    const int lrow1 = lrow0 + 8;
    const uint32_t lmrow = (uint32_t)(lane & 15) * HROWB + ((lane >> 4) << 4);

    const int ch = tid & 7;
    const int rb = tid >> 3;

#pragma unroll
    for (int i = 0; i < 4; i++) {
        int r = rb + i * 16;
        cp_async16(ps_b + (uint32_t)r * HROWB + ch * 16,
                   Qbase + (size_t)r * HD + ch * 8);
    }
    CP_COMMIT();

    auto issue_tile = [&](int kb) {
        uint32_t k_s = sb + (kb & 1) * 2 * FT_BYTES;
        uint32_t v_s = k_s + FT_BYTES;
#pragma unroll
        for (int i = 0; i < 4; i++) {
            int r = rb + i * 16;
            uint32_t so = (uint32_t)r * HROWB + ch * 16;
            size_t g = (size_t)(kb * 64 + r) * HD + ch * 8;
            cp_async16(k_s + so, Kbase + g);
            cp_async16(v_s + so, Vbase + g);
        }
        CP_COMMIT();
    };

    issue_tile(0);

    CP_WAIT1();        // Q resident (tile0 may still be in flight)
    __syncthreads();
    uint32_t qf[4][4];
    {
        const char* p0 = (const char*)fsm + 4 * FT_BYTES + lrow0 * HROWB;
        const char* p1 = (const char*)fsm + 4 * FT_BYTES + lrow1 * HROWB;
#pragma unroll
        for (int kt = 0; kt < 4; kt++) {
            qf[kt][0] = *(const uint32_t*)(p0 + 4 * lk + 32 * kt);
            qf[kt][1] = *(const uint32_t*)(p1 + 4 * lk + 32 * kt);
            qf[kt][2] = *(const uint32_t*)(p0 + 4 * lk + 32 * kt + 16);
            qf[kt][3] = *(const uint32_t*)(p1 + 4 * lk + 32 * kt + 16);
        }
    }

    float o[8][4];
#pragma unroll
    for (int nt = 0; nt < 8; nt++)
#pragma unroll
        for (int j = 0; j < 4; j++) o[nt][j] = 0.f;
    float m0 = -INFINITY, m1 = -INFINITY, l0 = 0.f, l1 = 0.f;
    const float scale = 0.125f;

    for (int kb = 0; kb <= qb; kb++) {
        CP_WAIT0();            // tile kb resident
        __syncthreads();       // all warps done with buffer being refilled
        if (kb + 1 <= qb)
            issue_tile(kb + 1);    // overlaps compute below

        const uint32_t ks_b = sb + (kb & 1) * 2 * FT_BYTES;
        const uint32_t vs_b = ks_b + FT_BYTES;

        float s[8][4];
#pragma unroll
        for (int nt = 0; nt < 8; nt++)
#pragma unroll
            for (int j = 0; j < 4; j++) s[nt][j] = 0.f;
#pragma unroll
        for (int pr = 0; pr < 4; pr++) {
            uint32_t base = ks_b + (uint32_t)(pr * 16) * HROWB + lmrow;
#pragma unroll
            for (int kt = 0; kt < 4; kt++) {
                uint32_t kf[4];
                ldsm_x4(kf, base + kt * 32);
                uint32_t b0[2] = {kf[0], kf[2]};
                uint32_t b1[2] = {kf[1], kf[3]};
                mma16n8k16(s[2 * pr], qf[kt], b0);
                mma16n8k16(s[2 * pr + 1], qf[kt], b1);
            }
        }

        if (kb == qb) {
#pragma unroll
            for (int nt = 0; nt < 8; nt++) {
                int c0 = nt * 8 + lk * 2, c1 = c0 + 1;
                s[nt][0] = (c0 > lrow0) ? -INFINITY : s[nt][0] * scale;
                s[nt][1] = (c1 > lrow0) ? -INFINITY : s[nt][1] * scale;
                s[nt][2] = (c0 > lrow1) ? -INFINITY : s[nt][2] * scale;
                s[nt][3] = (c1 > lrow1) ? -INFINITY : s[nt][3] * scale;
            }
        } else {
#pragma unroll
            for (int nt = 0; nt < 8; nt++)
#pragma unroll
                for (int j = 0; j < 4; j++) s[nt][j] *= scale;
        }

        float mx0 = -INFINITY, mx1 = -INFINITY;
#pragma unroll
        for (int nt = 0; nt < 8; nt++) {
            mx0 = fmaxf(mx0, fmaxf(s[nt][0], s[nt][1]));
            mx1 = fmaxf(mx1, fmaxf(s[nt][2], s[nt][3]));
        }
        mx0 = fmaxf(mx0, __shfl_xor_sync(0xffffffffu, mx0, 1));
        mx0 = fmaxf(mx0, __shfl_xor_sync(0xffffffffu, mx0, 2));
        mx1 = fmaxf(mx1, __shfl_xor_sync(0xffffffffu, mx1, 1));
        mx1 = fmaxf(mx1, __shfl_xor_sync(0xffffffffu, mx1, 2));

        float mn0 = fmaxf(m0, mx0), mn1 = fmaxf(m1, mx1);
        float a0 = __expf(m0 - mn0), a1 = __expf(m1 - mn1);
        m0 = mn0; m1 = mn1;

        float rs0 = 0.f, rs1 = 0.f;
#pragma unroll
        for (int nt = 0; nt < 8; nt++) {
            s[nt][0] = __expf(s[nt][0] - mn0);
            s[nt][1] = __expf(s[nt][1] - mn0);
            s[nt][2] = __expf(s[nt][2] - mn1);
            s[nt][3] = __expf(s[nt][3] - mn1);
            rs0 += s[nt][0] + s[nt][1];
            rs1 += s[nt][2] + s[nt][3];
        }
        rs0 += __shfl_xor_sync(0xffffffffu, rs0, 1);
        rs0 += __shfl_xor_sync(0xffffffffu, rs0, 2);
        rs1 += __shfl_xor_sync(0xffffffffu, rs1, 1);
        rs1 += __shfl_xor_sync(0xffffffffu, rs1, 2);
        l0 = l0 * a0 + rs0;
        l1 = l1 * a1 + rs1;

#pragma unroll
        for (int nt = 0; nt < 8; nt++) {
            o[nt][0] *= a0; o[nt][1] *= a0;
            o[nt][2] *= a1; o[nt][3] *= a1;
        }

        uint32_t pf[4][4];
#pragma unroll
        for (int kt = 0; kt < 4; kt++) {
            pf[kt][0] = pack_h2(s[2 * kt][0],     s[2 * kt][1]);
            pf[kt][1] = pack_h2(s[2 * kt][2],     s[2 * kt][3]);
            pf[kt][2] = pack_h2(s[2 * kt + 1][0], s[2 * kt + 1][1]);
            pf[kt][3] = pack_h2(s[2 * kt + 1][2], s[2 * kt + 1][3]);
        }

#pragma unroll
        for (int nt = 0; nt < 8; nt++) {
#pragma unroll
            for (int g = 0; g < 2; g++) {
                uint32_t vb[4];
                ldsm_x4_t(vb, vs_b + (uint32_t)(32 * g + lane) * HROWB + nt * 16);
                mma16n8k16(o[nt], pf[2 * g], vb);
                mma16n8k16(o[nt], pf[2 * g + 1], vb + 2);
            }
        }
    }

    const int b = bh >> 4, h = bh & 15;
    const float inv0 = 1.0f / l0, inv1 = 1.0f / l1;
    const int t0 = qb * 64 + lrow0, t1 = qb * 64 + lrow1;
    __half* dst0 = Yg + ((size_t)(b * Tt + t0)) * Cc + h * 64;
    __half* dst1 = Yg + ((size_t)(b * Tt + t1)) * Cc + h * 64;
#pragma unroll
    for (int nt = 0; nt < 8; nt++) {
        int d = nt * 8 + lk * 2;
        *(__half2*)(dst0 + d) = __floats2half2_rn(o[nt][0] * inv0, o[nt][1] * inv0);
        *(__half2*)(dst1 + d) = __floats2half2_rn(o[nt][2] * inv1, o[nt][3] * inv1);
    }
}

// ---------------------------------------------------------------------------
extern "C" void kernel_launch(void* const* d_in, const int* in_sizes, int n_in,
                              void* d_out, int out_size)
{
    const float* xq = (const float*)d_in[0];
    const float* xk = (const float*)d_in[1];
    const float* xv = (const float*)d_in[2];
    const float* Wq = (const float*)d_in[3];
    const float* Wk = (const float*)d_in[4];
    const float* Wv = (const float*)d_in[5];
    const float* Wo = (const float*)d_in[6];
    const float* bo = (const float*)d_in[7];
    float* out = (float*)d_out;

    __half *hxq, *hxk, *hxv, *hWq, *hWk, *hWv, *hWo, *Qp, *Kp, *Vp, *Yp;
    cudaGetSymbolAddress((void**)&hxq, g_hxq);
    cudaGetSymbolAddress((void**)&hxk, g_hxk);
    cudaGetSymbolAddress((void**)&hxv, g_hxv);
    cudaGetSymbolAddress((void**)&hWq, g_hWq);
    cudaGetSymbolAddress((void**)&hWk, g_hWk);
    cudaGetSymbolAddress((void**)&hWv, g_hWv);
    cudaGetSymbolAddress((void**)&hWo, g_hWo);
    cudaGetSymbolAddress((void**)&Qp, g_Q);
    cudaGetSymbolAddress((void**)&Kp, g_K);
    cudaGetSymbolAddress((void**)&Vp, g_V);
    cudaGetSymbolAddress((void**)&Yp, g_Y);

    cudaFuncSetAttribute(qkv_gemm, cudaFuncAttributeMaxDynamicSharedMemorySize, GEMM_SMEM);
    cudaFuncSetAttribute(oproj_gemm, cudaFuncAttributeMaxDynamicSharedMemorySize, GEMM_SMEM);
    cudaFuncSetAttribute(flash_mma, cudaFuncAttributeMaxDynamicSharedMemorySize, FA_SMEM);

    CvtArgs ca;
    const int NX4 = Mrows * Cc / 4;
    const int NW4 = Cc * Cc / 4;
    ca.src[0] = (const float4*)xq; ca.dst[0] = (uint2*)hxq; ca.n4[0] = NX4;
    ca.src[1] = (const float4*)xk; ca.dst[1] = (uint2*)hxk; ca.n4[1] = NX4;
    ca.src[2] = (const float4*)xv; ca.dst[2] = (uint2*)hxv; ca.n4[2] = NX4;
    ca.src[3] = (const float4*)Wq; ca.dst[3] = (uint2*)hWq; ca.n4[3] = NW4;
    ca.src[4] = (const float4*)Wk; ca.dst[4] = (uint2*)hWk; ca.n4[4] = NW4;
    ca.src[5] = (const float4*)Wv; ca.dst[5] = (uint2*)hWv; ca.n4[5] = NW4;
    ca.src[6] = (const float4*)Wo; ca.dst[6] = (uint2*)hWo; ca.n4[6] = NW4;
    cvt_kernel<<<dim3(2048, 7), 256>>>(ca);

    QKVArgs qa;
    qa.A[0] = hxq; qa.W[0] = hWq; qa.out[0] = Qp;
    qa.A[1] = hxk; qa.W[1] = hWk; qa.out[1] = Kp;
    qa.A[2] = hxv; qa.W[2] = hWv; qa.out[2] = Vp;
    qkv_gemm<<<dim3(Cc / 128, Mrows / 128, 3), 256, GEMM_SMEM>>>(qa);

    flash_mma<<<dim3(Tt / 64, Bb * Hh), 128, FA_SMEM>>>(Qp, Kp, Vp, Yp);

    oproj_gemm<<<dim3(Cc / 128, Mrows / 128), 256, GEMM_SMEM>>>(Yp, hWo, bo, out);
}

// round 11
// speedup vs baseline: 1.0146x; 1.0146x over previous
#include <cuda_runtime.h>
#include <cuda_fp16.h>
#include <math.h>
#include <stdint.h>

// Problem constants
#define Bb 4
#define Tt 2048
#define Cc 1024
#define Hh 16
#define HD 64
#define Mrows (Bb*Tt)   // 8192
#define GK 1024

// ---------------------------------------------------------------------------
// Helpers
// ---------------------------------------------------------------------------
__device__ __forceinline__ uint32_t smem_u32(const void* p) {
    uint32_t a;
    asm("{ .reg .u64 t; cvta.to.shared.u64 t, %1; cvt.u32.u64 %0, t; }"
        : "=r"(a) : "l"(p));
    return a;
}

__device__ __forceinline__ void cp_async16(uint32_t dst, const void* src) {
    asm volatile("cp.async.cg.shared.global [%0], [%1], 16;"
                 :: "r"(dst), "l"(src) : "memory");
}
#define CP_COMMIT() asm volatile("cp.async.commit_group;" ::: "memory")
#define CP_WAIT0()  asm volatile("cp.async.wait_group 0;" ::: "memory")
#define CP_WAIT1()  asm volatile("cp.async.wait_group 1;" ::: "memory")

// mma.sync m16n8k16 fp16 inputs, fp32 accumulate
__device__ __forceinline__ void mma16n8k16(
    float* c, const uint32_t* a, const uint32_t* b)
{
    asm volatile(
        "mma.sync.aligned.m16n8k16.row.col.f32.f16.f16.f32 "
        "{%0,%1,%2,%3}, {%4,%5,%6,%7}, {%8,%9}, {%0,%1,%2,%3};"
        : "+f"(c[0]), "+f"(c[1]), "+f"(c[2]), "+f"(c[3])
        : "r"(a[0]), "r"(a[1]), "r"(a[2]), "r"(a[3]),
          "r"(b[0]), "r"(b[1]));
}

__device__ __forceinline__ void ldsm_x4(uint32_t* r, uint32_t addr) {
    asm volatile(
        "ldmatrix.sync.aligned.m8n8.x4.shared.b16 {%0,%1,%2,%3}, [%4];"
        : "=r"(r[0]), "=r"(r[1]), "=r"(r[2]), "=r"(r[3]) : "r"(addr));
}
__device__ __forceinline__ void ldsm_x4_t(uint32_t* r, uint32_t addr) {
    asm volatile(
        "ldmatrix.sync.aligned.m8n8.x4.trans.shared.b16 {%0,%1,%2,%3}, [%4];"
        : "=r"(r[0]), "=r"(r[1]), "=r"(r[2]), "=r"(r[3]) : "r"(addr));
}

__device__ __forceinline__ uint32_t pack_h2(float a, float b) {
    __half2 h = __floats2half2_rn(a, b);
    return *reinterpret_cast<uint32_t*>(&h);
}

// ---------------------------------------------------------------------------
// Scratch (allocation-free: __device__ globals)
// ---------------------------------------------------------------------------
__device__ __half g_hxq[(size_t)Mrows*Cc];
__device__ __half g_hxk[(size_t)Mrows*Cc];
__device__ __half g_hxv[(size_t)Mrows*Cc];
__device__ __half g_hWq[(size_t)Cc*Cc];
__device__ __half g_hWk[(size_t)Cc*Cc];
__device__ __half g_hWv[(size_t)Cc*Cc];
__device__ __half g_hWo[(size_t)Cc*Cc];
__device__ __half g_Q[(size_t)Bb*Hh*Tt*HD];
__device__ __half g_K[(size_t)Bb*Hh*Tt*HD];
__device__ __half g_V[(size_t)Bb*Hh*Tt*HD];
__device__ __half g_Y[(size_t)Bb*Tt*Cc];

// ---------------------------------------------------------------------------
// Batched fp32 -> fp16 convert, MLP=4
// ---------------------------------------------------------------------------
struct CvtArgs {
    const float4* src[7];
    uint2*        dst[7];
    int           n4[7];
};

__global__ __launch_bounds__(256) void cvt_kernel(CvtArgs a) {
    int j = blockIdx.y;
    const float4* __restrict__ s = a.src[j];
    uint2* __restrict__ d = a.dst[j];
    int n4 = a.n4[j];
    int stride = gridDim.x * blockDim.x;
    int i = blockIdx.x * blockDim.x + threadIdx.x;
    for (; i + 3 * stride < n4; i += 4 * stride) {
        float4 v0 = s[i];
        float4 v1 = s[i + stride];
        float4 v2 = s[i + 2 * stride];
        float4 v3 = s[i + 3 * stride];
        uint2 o0, o1, o2, o3;
        o0.x = pack_h2(v0.x, v0.y); o0.y = pack_h2(v0.z, v0.w);
        o1.x = pack_h2(v1.x, v1.y); o1.y = pack_h2(v1.z, v1.w);
        o2.x = pack_h2(v2.x, v2.y); o2.y = pack_h2(v2.z, v2.w);
        o3.x = pack_h2(v3.x, v3.y); o3.y = pack_h2(v3.z, v3.w);
        d[i] = o0;
        d[i + stride] = o1;
        d[i + 2 * stride] = o2;
        d[i + 3 * stride] = o3;
    }
    for (; i < n4; i += stride) {
        float4 v = s[i];
        uint2 o;
        o.x = pack_h2(v.x, v.y);
        o.y = pack_h2(v.z, v.w);
        d[i] = o;
    }
}

// ---------------------------------------------------------------------------
// GEMM core (exact R9 best): BM=128, BN=128, BK=64, 8 warps, warp 64x32.
// 2-stage cp.async, single __syncthreads per K-iteration.
// ---------------------------------------------------------------------------
#define HROWB 144               // bytes per smem row (72 halves)
#define GTILE (128*HROWB)       // 18432 B
#define GSTAGE (2*GTILE)        // 36864 B
#define GEMM_SMEM (2*GSTAGE)    // 73728 B
#define GKT (GK/64)             // 16

__device__ __forceinline__ void gemm_core(
    const __half* __restrict__ A, const __half* __restrict__ W,
    int bm, int bn, uint32_t sbase,
    int tid, int wm, int wn, int lane, float c[4][4][4])
{
#pragma unroll
    for (int i = 0; i < 4; i++)
#pragma unroll
        for (int j = 0; j < 4; j++)
#pragma unroll
            for (int r = 0; r < 4; r++) c[i][j][r] = 0.f;

    const int ch = tid & 7;
    const int rb = tid >> 3;
    const uint32_t lmrow = (uint32_t)(lane & 15) * HROWB + ((lane >> 4) << 4);

    auto issue_stage = [&](int stage, int k0) {
        uint32_t a_s = sbase + stage * GSTAGE;
        uint32_t b_s = a_s + GTILE;
#pragma unroll
        for (int i = 0; i < 4; i++) {
            int r = rb + i * 32;
            uint32_t so = (uint32_t)r * HROWB + ch * 16;
            cp_async16(a_s + so, A + (size_t)(bm + r) * GK + k0 + ch * 8);
            cp_async16(b_s + so, W + (size_t)(bn + r) * GK + k0 + ch * 8);
        }
        CP_COMMIT();
    };

    issue_stage(0, 0);

    for (int it = 0; it < GKT; ++it) {
        CP_WAIT0();            // stage it resident
        __syncthreads();       // all warps done with stage it-1 buffer
        if (it + 1 < GKT)
            issue_stage((it + 1) & 1, (it + 1) * 64);   // overlaps MMA below

        uint32_t as_b = sbase + (it & 1) * GSTAGE;
        uint32_t bs_b = as_b + GTILE;

#pragma unroll
        for (int ks = 0; ks < 4; ks++) {
            uint32_t af[4][4], bf[2][4];
#pragma unroll
            for (int mt = 0; mt < 4; mt++)
                ldsm_x4(af[mt],
                        as_b + (uint32_t)(wm * 64 + mt * 16) * HROWB + lmrow + ks * 32);
#pragma unroll
            for (int pr = 0; pr < 2; pr++)
                ldsm_x4(bf[pr],
                        bs_b + (uint32_t)(wn * 32 + pr * 16) * HROWB + lmrow + ks * 32);
#pragma unroll
            for (int mt = 0; mt < 4; mt++)
#pragma unroll
                for (int nt = 0; nt < 4; nt++) {
                    uint32_t b2[2];
                    b2[0] = bf[nt >> 1][nt & 1];
                    b2[1] = bf[nt >> 1][(nt & 1) + 2];
                    mma16n8k16(c[mt][nt], af[mt], b2);
                }
        }
    }
}

// Merged Q/K/V projection
struct QKVArgs {
    const __half* A[3];
    const __half* W[3];
    __half*       out[3];
};

__global__ __launch_bounds__(256, 2) void qkv_gemm(QKVArgs args)
{
    extern __shared__ __align__(16) char dsm[];
    const int tid = threadIdx.x;
    const int wid = tid >> 5, lane = tid & 31;
    const int wm = wid & 1, wn = wid >> 1;
    const int bm = blockIdx.y * 128, bn = blockIdx.x * 128;
    const int g = blockIdx.z;
    const int lg = lane >> 2, lk = lane & 3;

    float c[4][4][4];
    gemm_core(args.A[g], args.W[g], bm, bn, smem_u32(dsm),
              tid, wm, wn, lane, c);

    __half* out = args.out[g];
#pragma unroll
    for (int mt = 0; mt < 4; mt++) {
        int r0 = bm + wm * 64 + mt * 16 + lg;
#pragma unroll
        for (int nt = 0; nt < 4; nt++) {
            int n = bn + wn * 32 + nt * 8 + lk * 2;
            int h = n >> 6, d = n & 63;
            int b0 = r0 >> 11, t0 = r0 & (Tt - 1);
            *(__half2*)(out + ((size_t)(b0 * Hh + h) * Tt + t0) * HD + d) =
                __floats2half2_rn(c[mt][nt][0], c[mt][nt][1]);
            int r1 = r0 + 8;
            int b1 = r1 >> 11, t1 = r1 & (Tt - 1);
            *(__half2*)(out + ((size_t)(b1 * Hh + h) * Tt + t1) * HD + d) =
                __floats2half2_rn(c[mt][nt][2], c[mt][nt][3]);
        }
    }
}

// O-projection: fp32 out + bias
__global__ __launch_bounds__(256, 2) void oproj_gemm(
    const __half* __restrict__ A, const __half* __restrict__ W,
    const float* __restrict__ bias, float* __restrict__ out)
{
    extern __shared__ __align__(16) char dsm[];
    const int tid = threadIdx.x;
    const int wid = tid >> 5, lane = tid & 31;
    const int wm = wid & 1, wn = wid >> 1;
    const int bm = blockIdx.y * 128, bn = blockIdx.x * 128;
    const int lg = lane >> 2, lk = lane & 3;

    float c[4][4][4];
    gemm_core(A, W, bm, bn, smem_u32(dsm), tid, wm, wn, lane, c);

#pragma unroll
    for (int mt = 0; mt < 4; mt++) {
        int r0 = bm + wm * 64 + mt * 16 + lg;
#pragma unroll
        for (int nt = 0; nt < 4; nt++) {
            int n = bn + wn * 32 + nt * 8 + lk * 2;
            float2 bv = *(const float2*)(bias + n);
            *(float2*)(out + (size_t)r0 * Cc + n) =
                make_float2(c[mt][nt][0] + bv.x, c[mt][nt][1] + bv.y);
            *(float2*)(out + (size_t)(r0 + 8) * Cc + n) =
                make_float2(c[mt][nt][2] + bv.x, c[mt][nt][3] + bv.y);
        }
    }
}

// ---------------------------------------------------------------------------
// fp16 tensor-core causal flash attention, 128 query rows per CTA.
// 256 threads (8 warps x 16 rows); K/V tiles of 64 keys, double-buffered.
// LPT: blockIdx.x reversed so longest CTAs launch first.
// ---------------------------------------------------------------------------
#define FT2 (64*HROWB)            // 9216 B (one 64x64 half tile)
#define QT2 (128*HROWB)           // 18432 B (Q: 128 rows)
#define FA_SMEM (4*FT2 + QT2)     // 55296 B

__global__ __launch_bounds__(256, 2) void flash_mma(
    const __half* __restrict__ Qg, const __half* __restrict__ Kg,
    const __half* __restrict__ Vg, __half* __restrict__ Yg)
{
    extern __shared__ __align__(16) char fsm[];
    const uint32_t sb = smem_u32(fsm);
    const uint32_t q_b = sb + 4 * FT2;

    const int tid = threadIdx.x;
    const int w = tid >> 5, lane = tid & 31;
    const int lg = lane >> 2, lk = lane & 3;
    const int qb = gridDim.x - 1 - blockIdx.x;   // LPT: long blocks first
    const int bh = blockIdx.y;

    const __half* Qbase = Qg + ((size_t)bh * Tt + qb * 128) * HD;
    const __half* Kbase = Kg + (size_t)bh * Tt * HD;
    const __half* Vbase = Vg + (size_t)bh * Tt * HD;

    const int lrow0 = w * 16 + lg;        // 0..127
    const int lrow1 = lrow0 + 8;
    const uint32_t lmrow = (uint32_t)(lane & 15) * HROWB + ((lane >> 4) << 4);

    // ---- stage Q (128 rows x 128B): 4 chunks per thread ----
#pragma unroll
    for (int i = 0; i < 4; i++) {
        int idx = tid + i * 256;
        int r = idx >> 3, ch8 = idx & 7;
        cp_async16(q_b + (uint32_t)r * HROWB + ch8 * 16,
                   Qbase + (size_t)r * HD + ch8 * 8);
    }
    CP_COMMIT();

    auto issue_tile = [&](int kb) {
        uint32_t k_s = sb + (kb & 1) * 2 * FT2;
        uint32_t v_s = k_s + FT2;
#pragma unroll
        for (int i = 0; i < 2; i++) {
            int idx = tid + i * 256;
            int r = idx >> 3, ch8 = idx & 7;
            uint32_t so = (uint32_t)r * HROWB + ch8 * 16;
            size_t g = (size_t)(kb * 64 + r) * HD + ch8 * 8;
            cp_async16(k_s + so, Kbase + g);
            cp_async16(v_s + so, Vbase + g);
        }
        CP_COMMIT();
    };

    issue_tile(0);

    CP_WAIT1();        // Q resident (tile0 may still be in flight)
    __syncthreads();
    uint32_t qf[4][4];
    {
        const uint32_t p0 = q_b + (uint32_t)lrow0 * HROWB;
        const uint32_t p1 = q_b + (uint32_t)lrow1 * HROWB;
#pragma unroll
        for (int kt = 0; kt < 4; kt++) {
            qf[kt][0] = *(const uint32_t*)(fsm + (p0 - sb) + 4 * lk + 32 * kt);
            qf[kt][1] = *(const uint32_t*)(fsm + (p1 - sb) + 4 * lk + 32 * kt);
            qf[kt][2] = *(const uint32_t*)(fsm + (p0 - sb) + 4 * lk + 32 * kt + 16);
            qf[kt][3] = *(const uint32_t*)(fsm + (p1 - sb) + 4 * lk + 32 * kt + 16);
        }
    }

    float o[8][4];
#pragma unroll
    for (int nt = 0; nt < 8; nt++)
#pragma unroll
        for (int j = 0; j < 4; j++) o[nt][j] = 0.f;
    float m0 = -INFINITY, m1 = -INFINITY, l0 = 0.f, l1 = 0.f;
    const float scale = 0.125f;

    const int kbmax = 2 * qb + 1;
    const int grow0 = qb * 128 + lrow0;   // global query rows of this thread
    const int grow1 = grow0 + 8;
    const int wrow_min = qb * 128 + w * 16;        // warp's smallest row
    const int wrow_max = wrow_min + 15;

    for (int kb = 0; kb <= kbmax; kb++) {
        CP_WAIT0();            // tile kb resident
        __syncthreads();       // all warps done with buffer being refilled
        if (kb + 1 <= kbmax)
            issue_tile(kb + 1);    // overlaps compute below

        // warp entirely above diagonal for this tile -> no contribution
        if (kb * 64 > wrow_max) continue;   // no barriers below

        const uint32_t ks_b = sb + (kb & 1) * 2 * FT2;
        const uint32_t vs_b = ks_b + FT2;

        // ---- S = Q @ K^T ----
        float s[8][4];
#pragma unroll
        for (int nt = 0; nt < 8; nt++)
#pragma unroll
            for (int j = 0; j < 4; j++) s[nt][j] = 0.f;
#pragma unroll
        for (int pr = 0; pr < 4; pr++) {
            uint32_t base = ks_b + (uint32_t)(pr * 16) * HROWB + lmrow;
#pragma unroll
            for (int kt = 0; kt < 4; kt++) {
                uint32_t kf[4];
                ldsm_x4(kf, base + kt * 32);
                uint32_t b0[2] = {kf[0], kf[2]};
                uint32_t b1[2] = {kf[1], kf[3]};
                mma16n8k16(s[2 * pr], qf[kt], b0);
                mma16n8k16(s[2 * pr + 1], qf[kt], b1);
            }
        }

        // ---- scale + causal mask (only tiles crossing this warp's rows) ----
        if (kb * 64 + 63 > wrow_min) {
#pragma unroll
            for (int nt = 0; nt < 8; nt++) {
                int c0 = kb * 64 + nt * 8 + lk * 2, c1 = c0 + 1;
                s[nt][0] = (c0 > grow0) ? -INFINITY : s[nt][0] * scale;
                s[nt][1] = (c1 > grow0) ? -INFINITY : s[nt][1] * scale;
                s[nt][2] = (c0 > grow1) ? -INFINITY : s[nt][2] * scale;
                s[nt][3] = (c1 > grow1) ? -INFINITY : s[nt][3] * scale;
            }
        } else {
#pragma unroll
            for (int nt = 0; nt < 8; nt++)
#pragma unroll
                for (int j = 0; j < 4; j++) s[nt][j] *= scale;
        }

        // ---- online softmax ----
        float mx0 = -INFINITY, mx1 = -INFINITY;
#pragma unroll
        for (int nt = 0; nt < 8; nt++) {
            mx0 = fmaxf(mx0, fmaxf(s[nt][0], s[nt][1]));
            mx1 = fmaxf(mx1, fmaxf(s[nt][2], s[nt][3]));
        }
        mx0 = fmaxf(mx0, __shfl_xor_sync(0xffffffffu, mx0, 1));
        mx0 = fmaxf(mx0, __shfl_xor_sync(0xffffffffu, mx0, 2));
        mx1 = fmaxf(mx1, __shfl_xor_sync(0xffffffffu, mx1, 1));
        mx1 = fmaxf(mx1, __shfl_xor_sync(0xffffffffu, mx1, 2));

        float mn0 = fmaxf(m0, mx0), mn1 = fmaxf(m1, mx1);
        float a0 = __expf(m0 - mn0), a1 = __expf(m1 - mn1);
        m0 = mn0; m1 = mn1;

        float rs0 = 0.f, rs1 = 0.f;
#pragma unroll
        for (int nt = 0; nt < 8; nt++) {
            s[nt][0] = __expf(s[nt][0] - mn0);
            s[nt][1] = __expf(s[nt][1] - mn0);
            s[nt][2] = __expf(s[nt][2] - mn1);
            s[nt][3] = __expf(s[nt][3] - mn1);
            rs0 += s[nt][0] + s[nt][1];
            rs1 += s[nt][2] + s[nt][3];
        }
        rs0 += __shfl_xor_sync(0xffffffffu, rs0, 1);
        rs0 += __shfl_xor_sync(0xffffffffu, rs0, 2);
        rs1 += __shfl_xor_sync(0xffffffffu, rs1, 1);
        rs1 += __shfl_xor_sync(0xffffffffu, rs1, 2);
        l0 = l0 * a0 + rs0;
        l1 = l1 * a1 + rs1;

#pragma unroll
        for (int nt = 0; nt < 8; nt++) {
            o[nt][0] *= a0; o[nt][1] *= a0;
            o[nt][2] *= a1; o[nt][3] *= a1;
        }

        // ---- P fragments directly from S registers (C-layout == A-layout) ----
        uint32_t pf[4][4];
#pragma unroll
        for (int kt = 0; kt < 4; kt++) {
            pf[kt][0] = pack_h2(s[2 * kt][0],     s[2 * kt][1]);
            pf[kt][1] = pack_h2(s[2 * kt][2],     s[2 * kt][3]);
            pf[kt][2] = pack_h2(s[2 * kt + 1][0], s[2 * kt + 1][1]);
            pf[kt][3] = pack_h2(s[2 * kt + 1][2], s[2 * kt + 1][3]);
        }

        // ---- O += P @ V ----
#pragma unroll
        for (int nt = 0; nt < 8; nt++) {
#pragma unroll
            for (int g = 0; g < 2; g++) {
                uint32_t vb[4];
                ldsm_x4_t(vb, vs_b + (uint32_t)(32 * g + lane) * HROWB + nt * 16);
                mma16n8k16(o[nt], pf[2 * g], vb);
                mma16n8k16(o[nt], pf[2 * g + 1], vb + 2);
            }
        }
    }

    // ---- epilogue ----
    const int b = bh >> 4, h = bh & 15;
    const float inv0 = 1.0f / l0, inv1 = 1.0f / l1;
    const int t0 = qb * 128 + lrow0, t1 = qb * 128 + lrow1;
    __half* dst0 = Yg + ((size_t)(b * Tt + t0)) * Cc + h * 64;
    __half* dst1 = Yg + ((size_t)(b * Tt + t1)) * Cc + h * 64;
#pragma unroll
    for (int nt = 0; nt < 8; nt++) {
        int d = nt * 8 + lk * 2;
        *(__half2*)(dst0 + d) = __floats2half2_rn(o[nt][0] * inv0, o[nt][1] * inv0);
        *(__half2*)(dst1 + d) = __floats2half2_rn(o[nt][2] * inv1, o[nt][3] * inv1);
    }
}

// ---------------------------------------------------------------------------
extern "C" void kernel_launch(void* const* d_in, const int* in_sizes, int n_in,
                              void* d_out, int out_size)
{
    const float* xq = (const float*)d_in[0];
    const float* xk = (const float*)d_in[1];
    const float* xv = (const float*)d_in[2];
    const float* Wq = (const float*)d_in[3];
    const float* Wk = (const float*)d_in[4];
    const float* Wv = (const float*)d_in[5];
    const float* Wo = (const float*)d_in[6];
    const float* bo = (const float*)d_in[7];
    float* out = (float*)d_out;

    __half *hxq, *hxk, *hxv, *hWq, *hWk, *hWv, *hWo, *Qp, *Kp, *Vp, *Yp;
    cudaGetSymbolAddress((void**)&hxq, g_hxq);
    cudaGetSymbolAddress((void**)&hxk, g_hxk);
    cudaGetSymbolAddress((void**)&hxv, g_hxv);
    cudaGetSymbolAddress((void**)&hWq, g_hWq);
    cudaGetSymbolAddress((void**)&hWk, g_hWk);
    cudaGetSymbolAddress((void**)&hWv, g_hWv);
    cudaGetSymbolAddress((void**)&hWo, g_hWo);
    cudaGetSymbolAddress((void**)&Qp, g_Q);
    cudaGetSymbolAddress((void**)&Kp, g_K);
    cudaGetSymbolAddress((void**)&Vp, g_V);
    cudaGetSymbolAddress((void**)&Yp, g_Y);

    cudaFuncSetAttribute(qkv_gemm, cudaFuncAttributeMaxDynamicSharedMemorySize, GEMM_SMEM);
    cudaFuncSetAttribute(oproj_gemm, cudaFuncAttributeMaxDynamicSharedMemorySize, GEMM_SMEM);
    cudaFuncSetAttribute(flash_mma, cudaFuncAttributeMaxDynamicSharedMemorySize, FA_SMEM);

    CvtArgs ca;
    const int NX4 = Mrows * Cc / 4;
    const int NW4 = Cc * Cc / 4;
    ca.src[0] = (const float4*)xq; ca.dst[0] = (uint2*)hxq; ca.n4[0] = NX4;
    ca.src[1] = (const float4*)xk; ca.dst[1] = (uint2*)hxk; ca.n4[1] = NX4;
    ca.src[2] = (const float4*)xv; ca.dst[2] = (uint2*)hxv; ca.n4[2] = NX4;
    ca.src[3] = (const float4*)Wq; ca.dst[3] = (uint2*)hWq; ca.n4[3] = NW4;
    ca.src[4] = (const float4*)Wk; ca.dst[4] = (uint2*)hWk; ca.n4[4] = NW4;
    ca.src[5] = (const float4*)Wv; ca.dst[5] = (uint2*)hWv; ca.n4[5] = NW4;
    ca.src[6] = (const float4*)Wo; ca.dst[6] = (uint2*)hWo; ca.n4[6] = NW4;
    cvt_kernel<<<dim3(2048, 7), 256>>>(ca);

    QKVArgs qa;
    qa.A[0] = hxq; qa.W[0] = hWq; qa.out[0] = Qp;
    qa.A[1] = hxk; qa.W[1] = hWk; qa.out[1] = Kp;
    qa.A[2] = hxv; qa.W[2] = hWv; qa.out[2] = Vp;
    qkv_gemm<<<dim3(Cc / 128, Mrows / 128, 3), 256, GEMM_SMEM>>>(qa);

    flash_mma<<<dim3(Tt / 128, Bb * Hh), 256, FA_SMEM>>>(Qp, Kp, Vp, Yp);

    oproj_gemm<<<dim3(Cc / 128, Mrows / 128), 256, GEMM_SMEM>>>(Yp, hWo, bo, out);
}

// round 12
// speedup vs baseline: 1.0225x; 1.0078x over previous
#include <cuda_runtime.h>
#include <cuda_fp16.h>
#include <math.h>
#include <stdint.h>

// Problem constants
#define Bb 4
#define Tt 2048
#define Cc 1024
#define Hh 16
#define HD 64
#define Mrows (Bb*Tt)   // 8192
#define GK 1024

// ---------------------------------------------------------------------------
// Helpers
// ---------------------------------------------------------------------------
__device__ __forceinline__ uint32_t smem_u32(const void* p) {
    uint32_t a;
    asm("{ .reg .u64 t; cvta.to.shared.u64 t, %1; cvt.u32.u64 %0, t; }"
        : "=r"(a) : "l"(p));
    return a;
}

__device__ __forceinline__ void cp_async16(uint32_t dst, const void* src) {
    asm volatile("cp.async.cg.shared.global [%0], [%1], 16;"
                 :: "r"(dst), "l"(src) : "memory");
}
#define CP_COMMIT() asm volatile("cp.async.commit_group;" ::: "memory")
#define CP_WAIT0()  asm volatile("cp.async.wait_group 0;" ::: "memory")
#define CP_WAIT1()  asm volatile("cp.async.wait_group 1;" ::: "memory")

// mma.sync m16n8k16 fp16 inputs, fp32 accumulate
__device__ __forceinline__ void mma16n8k16(
    float* c, const uint32_t* a, const uint32_t* b)
{
    asm volatile(
        "mma.sync.aligned.m16n8k16.row.col.f32.f16.f16.f32 "
        "{%0,%1,%2,%3}, {%4,%5,%6,%7}, {%8,%9}, {%0,%1,%2,%3};"
        : "+f"(c[0]), "+f"(c[1]), "+f"(c[2]), "+f"(c[3])
        : "r"(a[0]), "r"(a[1]), "r"(a[2]), "r"(a[3]),
          "r"(b[0]), "r"(b[1]));
}

__device__ __forceinline__ void ldsm_x4(uint32_t* r, uint32_t addr) {
    asm volatile(
        "ldmatrix.sync.aligned.m8n8.x4.shared.b16 {%0,%1,%2,%3}, [%4];"
        : "=r"(r[0]), "=r"(r[1]), "=r"(r[2]), "=r"(r[3]) : "r"(addr));
}
__device__ __forceinline__ void ldsm_x4_t(uint32_t* r, uint32_t addr) {
    asm volatile(
        "ldmatrix.sync.aligned.m8n8.x4.trans.shared.b16 {%0,%1,%2,%3}, [%4];"
        : "=r"(r[0]), "=r"(r[1]), "=r"(r[2]), "=r"(r[3]) : "r"(addr));
}

__device__ __forceinline__ uint32_t pack_h2(float a, float b) {
    __half2 h = __floats2half2_rn(a, b);
    return *reinterpret_cast<uint32_t*>(&h);
}

// ---------------------------------------------------------------------------
// Scratch (allocation-free: __device__ globals)
// ---------------------------------------------------------------------------
__device__ __half g_hxq[(size_t)Mrows*Cc];
__device__ __half g_hxk[(size_t)Mrows*Cc];
__device__ __half g_hxv[(size_t)Mrows*Cc];
__device__ __half g_hWq[(size_t)Cc*Cc];
__device__ __half g_hWk[(size_t)Cc*Cc];
__device__ __half g_hWv[(size_t)Cc*Cc];
__device__ __half g_hWo[(size_t)Cc*Cc];
__device__ __half g_Q[(size_t)Bb*Hh*Tt*HD];
__device__ __half g_K[(size_t)Bb*Hh*Tt*HD];
__device__ __half g_V[(size_t)Bb*Hh*Tt*HD];
__device__ __half g_Y[(size_t)Bb*Tt*Cc];

// ---------------------------------------------------------------------------
// Batched fp32 -> fp16 convert, MLP=4
// ---------------------------------------------------------------------------
struct CvtArgs {
    const float4* src[7];
    uint2*        dst[7];
    int           n4[7];
};

__global__ __launch_bounds__(256) void cvt_kernel(CvtArgs a) {
    int j = blockIdx.y;
    const float4* __restrict__ s = a.src[j];
    uint2* __restrict__ d = a.dst[j];
    int n4 = a.n4[j];
    int stride = gridDim.x * blockDim.x;
    int i = blockIdx.x * blockDim.x + threadIdx.x;
    for (; i + 3 * stride < n4; i += 4 * stride) {
        float4 v0 = s[i];
        float4 v1 = s[i + stride];
        float4 v2 = s[i + 2 * stride];
        float4 v3 = s[i + 3 * stride];
        uint2 o0, o1, o2, o3;
        o0.x = pack_h2(v0.x, v0.y); o0.y = pack_h2(v0.z, v0.w);
        o1.x = pack_h2(v1.x, v1.y); o1.y = pack_h2(v1.z, v1.w);
        o2.x = pack_h2(v2.x, v2.y); o2.y = pack_h2(v2.z, v2.w);
        o3.x = pack_h2(v3.x, v3.y); o3.y = pack_h2(v3.z, v3.w);
        d[i] = o0;
        d[i + stride] = o1;
        d[i + 2 * stride] = o2;
        d[i + 3 * stride] = o3;
    }
    for (; i < n4; i += stride) {
        float4 v = s[i];
        uint2 o;
        o.x = pack_h2(v.x, v.y);
        o.y = pack_h2(v.z, v.w);
        d[i] = o;
    }
}

// ---------------------------------------------------------------------------
// GEMM core: BM=128, BN=64, BK=64. 8 warps as 4m x 2n, warp tile 32x32.
// Accum 32 regs/thread -> 3 CTAs/SM (24 warps). 2-stage cp.async.
// ---------------------------------------------------------------------------
#define HROWB 144               // bytes per smem row (72 halves)
#define ATILE (128*HROWB)       // 18432 B
#define BTILE (64*HROWB)        // 9216 B
#define GSTAGE (ATILE+BTILE)    // 27648 B
#define GEMM_SMEM (2*GSTAGE)    // 55296 B
#define GKT (GK/64)             // 16

__device__ __forceinline__ void gemm_core(
    const __half* __restrict__ A, const __half* __restrict__ W,
    int bm, int bn, uint32_t sbase,
    int tid, int wm, int wn, int lane, float c[2][4][4])
{
#pragma unroll
    for (int i = 0; i < 2; i++)
#pragma unroll
        for (int j = 0; j < 4; j++)
#pragma unroll
            for (int r = 0; r < 4; r++) c[i][j][r] = 0.f;

    const int ch = tid & 7;
    const int rb = tid >> 3;
    const uint32_t lmrow = (uint32_t)(lane & 15) * HROWB + ((lane >> 4) << 4);

    auto issue_stage = [&](int stage, int k0) {
        uint32_t a_s = sbase + stage * GSTAGE;
        uint32_t b_s = a_s + ATILE;
#pragma unroll
        for (int i = 0; i < 4; i++) {
            int r = rb + i * 32;
            cp_async16(a_s + (uint32_t)r * HROWB + ch * 16,
                       A + (size_t)(bm + r) * GK + k0 + ch * 8);
        }
#pragma unroll
        for (int i = 0; i < 2; i++) {
            int r = rb + i * 32;
            cp_async16(b_s + (uint32_t)r * HROWB + ch * 16,
                       W + (size_t)(bn + r) * GK + k0 + ch * 8);
        }
        CP_COMMIT();
    };

    issue_stage(0, 0);

    for (int it = 0; it < GKT; ++it) {
        CP_WAIT0();            // stage it resident
        __syncthreads();       // all warps done with stage it-1 buffer
        if (it + 1 < GKT)
            issue_stage((it + 1) & 1, (it + 1) * 64);   // overlaps MMA below

        uint32_t as_b = sbase + (it & 1) * GSTAGE;
        uint32_t bs_b = as_b + ATILE;

#pragma unroll
        for (int ks = 0; ks < 4; ks++) {
            uint32_t af[2][4], bf[2][4];
#pragma unroll
            for (int mt = 0; mt < 2; mt++)
                ldsm_x4(af[mt],
                        as_b + (uint32_t)(wm * 32 + mt * 16) * HROWB + lmrow + ks * 32);
#pragma unroll
            for (int pr = 0; pr < 2; pr++)
                ldsm_x4(bf[pr],
                        bs_b + (uint32_t)(wn * 32 + pr * 16) * HROWB + lmrow + ks * 32);
#pragma unroll
            for (int mt = 0; mt < 2; mt++)
#pragma unroll
                for (int nt = 0; nt < 4; nt++) {
                    uint32_t b2[2];
                    b2[0] = bf[nt >> 1][nt & 1];
                    b2[1] = bf[nt >> 1][(nt & 1) + 2];
                    mma16n8k16(c[mt][nt], af[mt], b2);
                }
        }
    }
}

// Merged Q/K/V projection
struct QKVArgs {
    const __half* A[3];
    const __half* W[3];
    __half*       out[3];
};

__global__ __launch_bounds__(256, 3) void qkv_gemm(QKVArgs args)
{
    extern __shared__ __align__(16) char dsm[];
    const int tid = threadIdx.x;
    const int wid = tid >> 5, lane = tid & 31;
    const int wm = wid & 3, wn = wid >> 2;     // 4m x 2n warp grid
    const int bm = blockIdx.y * 128, bn = blockIdx.x * 64;
    const int g = blockIdx.z;
    const int lg = lane >> 2, lk = lane & 3;

    float c[2][4][4];
    gemm_core(args.A[g], args.W[g], bm, bn, smem_u32(dsm),
              tid, wm, wn, lane, c);

    __half* out = args.out[g];
#pragma unroll
    for (int mt = 0; mt < 2; mt++) {
        int r0 = bm + wm * 32 + mt * 16 + lg;
#pragma unroll
        for (int nt = 0; nt < 4; nt++) {
            int n = bn + wn * 32 + nt * 8 + lk * 2;
            int h = n >> 6, d = n & 63;
            int b0 = r0 >> 11, t0 = r0 & (Tt - 1);
            *(__half2*)(out + ((size_t)(b0 * Hh + h) * Tt + t0) * HD + d) =
                __floats2half2_rn(c[mt][nt][0], c[mt][nt][1]);
            int r1 = r0 + 8;
            int b1 = r1 >> 11, t1 = r1 & (Tt - 1);
            *(__half2*)(out + ((size_t)(b1 * Hh + h) * Tt + t1) * HD + d) =
                __floats2half2_rn(c[mt][nt][2], c[mt][nt][3]);
        }
    }
}

// O-projection: fp32 out + bias
__global__ __launch_bounds__(256, 3) void oproj_gemm(
    const __half* __restrict__ A, const __half* __restrict__ W,
    const float* __restrict__ bias, float* __restrict__ out)
{
    extern __shared__ __align__(16) char dsm[];
    const int tid = threadIdx.x;
    const int wid = tid >> 5, lane = tid & 31;
    const int wm = wid & 3, wn = wid >> 2;
    const int bm = blockIdx.y * 128, bn = blockIdx.x * 64;
    const int lg = lane >> 2, lk = lane & 3;

    float c[2][4][4];
    gemm_core(A, W, bm, bn, smem_u32(dsm), tid, wm, wn, lane, c);

#pragma unroll
    for (int mt = 0; mt < 2; mt++) {
        int r0 = bm + wm * 32 + mt * 16 + lg;
#pragma unroll
        for (int nt = 0; nt < 4; nt++) {
            int n = bn + wn * 32 + nt * 8 + lk * 2;
            float2 bv = *(const float2*)(bias + n);
            *(float2*)(out + (size_t)r0 * Cc + n) =
                make_float2(c[mt][nt][0] + bv.x, c[mt][nt][1] + bv.y);
            *(float2*)(out + (size_t)(r0 + 8) * Cc + n) =
                make_float2(c[mt][nt][2] + bv.x, c[mt][nt][3] + bv.y);
        }
    }
}

// ---------------------------------------------------------------------------
// fp16 tensor-core causal flash attention, 128 query rows per CTA (R11).
// ---------------------------------------------------------------------------
#define FT2 (64*HROWB)            // 9216 B (one 64x64 half tile)
#define QT2 (128*HROWB)           // 18432 B (Q: 128 rows)
#define FA_SMEM (4*FT2 + QT2)     // 55296 B

__global__ __launch_bounds__(256, 2) void flash_mma(
    const __half* __restrict__ Qg, const __half* __restrict__ Kg,
    const __half* __restrict__ Vg, __half* __restrict__ Yg)
{
    extern __shared__ __align__(16) char fsm[];
    const uint32_t sb = smem_u32(fsm);
    const uint32_t q_b = sb + 4 * FT2;

    const int tid = threadIdx.x;
    const int w = tid >> 5, lane = tid & 31;
    const int lg = lane >> 2, lk = lane & 3;
    const int qb = gridDim.x - 1 - blockIdx.x;   // LPT: long blocks first
    const int bh = blockIdx.y;

    const __half* Qbase = Qg + ((size_t)bh * Tt + qb * 128) * HD;
    const __half* Kbase = Kg + (size_t)bh * Tt * HD;
    const __half* Vbase = Vg + (size_t)bh * Tt * HD;

    const int lrow0 = w * 16 + lg;        // 0..127
    const int lrow1 = lrow0 + 8;
    const uint32_t lmrow = (uint32_t)(lane & 15) * HROWB + ((lane >> 4) << 4);

#pragma unroll
    for (int i = 0; i < 4; i++) {
        int idx = tid + i * 256;
        int r = idx >> 3, ch8 = idx & 7;
        cp_async16(q_b + (uint32_t)r * HROWB + ch8 * 16,
                   Qbase + (size_t)r * HD + ch8 * 8);
    }
    CP_COMMIT();

    auto issue_tile = [&](int kb) {
        uint32_t k_s = sb + (kb & 1) * 2 * FT2;
        uint32_t v_s = k_s + FT2;
#pragma unroll
        for (int i = 0; i < 2; i++) {
            int idx = tid + i * 256;
            int r = idx >> 3, ch8 = idx & 7;
            uint32_t so = (uint32_t)r * HROWB + ch8 * 16;
            size_t g = (size_t)(kb * 64 + r) * HD + ch8 * 8;
            cp_async16(k_s + so, Kbase + g);
            cp_async16(v_s + so, Vbase + g);
        }
        CP_COMMIT();
    };

    issue_tile(0);

    CP_WAIT1();        // Q resident (tile0 may still be in flight)
    __syncthreads();
    uint32_t qf[4][4];
    {
        const char* p0 = fsm + 4 * FT2 + lrow0 * HROWB;
        const char* p1 = fsm + 4 * FT2 + lrow1 * HROWB;
#pragma unroll
        for (int kt = 0; kt < 4; kt++) {
            qf[kt][0] = *(const uint32_t*)(p0 + 4 * lk + 32 * kt);
            qf[kt][1] = *(const uint32_t*)(p1 + 4 * lk + 32 * kt);
            qf[kt][2] = *(const uint32_t*)(p0 + 4 * lk + 32 * kt + 16);
            qf[kt][3] = *(const uint32_t*)(p1 + 4 * lk + 32 * kt + 16);
        }
    }

    float o[8][4];
#pragma unroll
    for (int nt = 0; nt < 8; nt++)
#pragma unroll
        for (int j = 0; j < 4; j++) o[nt][j] = 0.f;
    float m0 = -INFINITY, m1 = -INFINITY, l0 = 0.f, l1 = 0.f;
    const float scale = 0.125f;

    const int kbmax = 2 * qb + 1;
    const int grow0 = qb * 128 + lrow0;
    const int grow1 = grow0 + 8;
    const int wrow_min = qb * 128 + w * 16;
    const int wrow_max = wrow_min + 15;

    for (int kb = 0; kb <= kbmax; kb++) {
        CP_WAIT0();
        __syncthreads();
        if (kb + 1 <= kbmax)
            issue_tile(kb + 1);

        if (kb * 64 > wrow_max) continue;   // fully masked for this warp

        const uint32_t ks_b = sb + (kb & 1) * 2 * FT2;
        const uint32_t vs_b = ks_b + FT2;

        float s[8][4];
#pragma unroll
        for (int nt = 0; nt < 8; nt++)
#pragma unroll
            for (int j = 0; j < 4; j++) s[nt][j] = 0.f;
#pragma unroll
        for (int pr = 0; pr < 4; pr++) {
            uint32_t base = ks_b + (uint32_t)(pr * 16) * HROWB + lmrow;
#pragma unroll
            for (int kt = 0; kt < 4; kt++) {
                uint32_t kf[4];
                ldsm_x4(kf, base + kt * 32);
                uint32_t b0[2] = {kf[0], kf[2]};
                uint32_t b1[2] = {kf[1], kf[3]};
                mma16n8k16(s[2 * pr], qf[kt], b0);
                mma16n8k16(s[2 * pr + 1], qf[kt], b1);
            }
        }

        if (kb * 64 + 63 > wrow_min) {
#pragma unroll
            for (int nt = 0; nt < 8; nt++) {
                int c0 = kb * 64 + nt * 8 + lk * 2, c1 = c0 + 1;
                s[nt][0] = (c0 > grow0) ? -INFINITY : s[nt][0] * scale;
                s[nt][1] = (c1 > grow0) ? -INFINITY : s[nt][1] * scale;
                s[nt][2] = (c0 > grow1) ? -INFINITY : s[nt][2] * scale;
                s[nt][3] = (c1 > grow1) ? -INFINITY : s[nt][3] * scale;
            }
        } else {
#pragma unroll
            for (int nt = 0; nt < 8; nt++)
#pragma unroll
                for (int j = 0; j < 4; j++) s[nt][j] *= scale;
        }

        float mx0 = -INFINITY, mx1 = -INFINITY;
#pragma unroll
        for (int nt = 0; nt < 8; nt++) {
            mx0 = fmaxf(mx0, fmaxf(s[nt][0], s[nt][1]));
            mx1 = fmaxf(mx1, fmaxf(s[nt][2], s[nt][3]));
        }
        mx0 = fmaxf(mx0, __shfl_xor_sync(0xffffffffu, mx0, 1));
        mx0 = fmaxf(mx0, __shfl_xor_sync(0xffffffffu, mx0, 2));
        mx1 = fmaxf(mx1, __shfl_xor_sync(0xffffffffu, mx1, 1));
        mx1 = fmaxf(mx1, __shfl_xor_sync(0xffffffffu, mx1, 2));

        float mn0 = fmaxf(m0, mx0), mn1 = fmaxf(m1, mx1);
        float a0 = __expf(m0 - mn0), a1 = __expf(m1 - mn1);
        m0 = mn0; m1 = mn1;

        float rs0 = 0.f, rs1 = 0.f;
#pragma unroll
        for (int nt = 0; nt < 8; nt++) {
            s[nt][0] = __expf(s[nt][0] - mn0);
            s[nt][1] = __expf(s[nt][1] - mn0);
            s[nt][2] = __expf(s[nt][2] - mn1);
            s[nt][3] = __expf(s[nt][3] - mn1);
            rs0 += s[nt][0] + s[nt][1];
            rs1 += s[nt][2] + s[nt][3];
        }
        rs0 += __shfl_xor_sync(0xffffffffu, rs0, 1);
        rs0 += __shfl_xor_sync(0xffffffffu, rs0, 2);
        rs1 += __shfl_xor_sync(0xffffffffu, rs1, 1);
        rs1 += __shfl_xor_sync(0xffffffffu, rs1, 2);
        l0 = l0 * a0 + rs0;
        l1 = l1 * a1 + rs1;

#pragma unroll
        for (int nt = 0; nt < 8; nt++) {
            o[nt][0] *= a0; o[nt][1] *= a0;
            o[nt][2] *= a1; o[nt][3] *= a1;
        }

        uint32_t pf[4][4];
#pragma unroll
        for (int kt = 0; kt < 4; kt++) {
            pf[kt][0] = pack_h2(s[2 * kt][0],     s[2 * kt][1]);
            pf[kt][1] = pack_h2(s[2 * kt][2],     s[2 * kt][3]);
            pf[kt][2] = pack_h2(s[2 * kt + 1][0], s[2 * kt + 1][1]);
            pf[kt][3] = pack_h2(s[2 * kt + 1][2], s[2 * kt + 1][3]);
        }

#pragma unroll
        for (int nt = 0; nt < 8; nt++) {
#pragma unroll
            for (int g = 0; g < 2; g++) {
                uint32_t vb[4];
                ldsm_x4_t(vb, vs_b + (uint32_t)(32 * g + lane) * HROWB + nt * 16);
                mma16n8k16(o[nt], pf[2 * g], vb);
                mma16n8k16(o[nt], pf[2 * g + 1], vb + 2);
            }
        }
    }

    const int b = bh >> 4, h = bh & 15;
    const float inv0 = 1.0f / l0, inv1 = 1.0f / l1;
    const int t0 = qb * 128 + lrow0, t1 = qb * 128 + lrow1;
    __half* dst0 = Yg + ((size_t)(b * Tt + t0)) * Cc + h * 64;
    __half* dst1 = Yg + ((size_t)(b * Tt + t1)) * Cc + h * 64;
#pragma unroll
    for (int nt = 0; nt < 8; nt++) {
        int d = nt * 8 + lk * 2;
        *(__half2*)(dst0 + d) = __floats2half2_rn(o[nt][0] * inv0, o[nt][1] * inv0);
        *(__half2*)(dst1 + d) = __floats2half2_rn(o[nt][2] * inv1, o[nt][3] * inv1);
    }
}

// ---------------------------------------------------------------------------
extern "C" void kernel_launch(void* const* d_in, const int* in_sizes, int n_in,
                              void* d_out, int out_size)
{
    const float* xq = (const float*)d_in[0];
    const float* xk = (const float*)d_in[1];
    const float* xv = (const float*)d_in[2];
    const float* Wq = (const float*)d_in[3];
    const float* Wk = (const float*)d_in[4];
    const float* Wv = (const float*)d_in[5];
    const float* Wo = (const float*)d_in[6];
    const float* bo = (const float*)d_in[7];
    float* out = (float*)d_out;

    __half *hxq, *hxk, *hxv, *hWq, *hWk, *hWv, *hWo, *Qp, *Kp, *Vp, *Yp;
    cudaGetSymbolAddress((void**)&hxq, g_hxq);
    cudaGetSymbolAddress((void**)&hxk, g_hxk);
    cudaGetSymbolAddress((void**)&hxv, g_hxv);
    cudaGetSymbolAddress((void**)&hWq, g_hWq);
    cudaGetSymbolAddress((void**)&hWk, g_hWk);
    cudaGetSymbolAddress((void**)&hWv, g_hWv);
    cudaGetSymbolAddress((void**)&hWo, g_hWo);
    cudaGetSymbolAddress((void**)&Qp, g_Q);
    cudaGetSymbolAddress((void**)&Kp, g_K);
    cudaGetSymbolAddress((void**)&Vp, g_V);
    cudaGetSymbolAddress((void**)&Yp, g_Y);

    cudaFuncSetAttribute(qkv_gemm, cudaFuncAttributeMaxDynamicSharedMemorySize, GEMM_SMEM);
    cudaFuncSetAttribute(oproj_gemm, cudaFuncAttributeMaxDynamicSharedMemorySize, GEMM_SMEM);
    cudaFuncSetAttribute(flash_mma, cudaFuncAttributeMaxDynamicSharedMemorySize, FA_SMEM);

    CvtArgs ca;
    const int NX4 = Mrows * Cc / 4;
    const int NW4 = Cc * Cc / 4;
    ca.src[0] = (const float4*)xq; ca.dst[0] = (uint2*)hxq; ca.n4[0] = NX4;
    ca.src[1] = (const float4*)xk; ca.dst[1] = (uint2*)hxk; ca.n4[1] = NX4;
    ca.src[2] = (const float4*)xv; ca.dst[2] = (uint2*)hxv; ca.n4[2] = NX4;
    ca.src[3] = (const float4*)Wq; ca.dst[3] = (uint2*)hWq; ca.n4[3] = NW4;
    ca.src[4] = (const float4*)Wk; ca.dst[4] = (uint2*)hWk; ca.n4[4] = NW4;
    ca.src[5] = (const float4*)Wv; ca.dst[5] = (uint2*)hWv; ca.n4[5] = NW4;
    ca.src[6] = (const float4*)Wo; ca.dst[6] = (uint2*)hWo; ca.n4[6] = NW4;
    cvt_kernel<<<dim3(2048, 7), 256>>>(ca);

    QKVArgs qa;
    qa.A[0] = hxq; qa.W[0] = hWq; qa.out[0] = Qp;
    qa.A[1] = hxk; qa.W[1] = hWk; qa.out[1] = Kp;
    qa.A[2] = hxv; qa.W[2] = hWv; qa.out[2] = Vp;
    qkv_gemm<<<dim3(Cc / 64, Mrows / 128, 3), 256, GEMM_SMEM>>>(qa);

    flash_mma<<<dim3(Tt / 128, Bb * Hh), 256, FA_SMEM>>>(Qp, Kp, Vp, Yp);

    oproj_gemm<<<dim3(Cc / 64, Mrows / 128), 256, GEMM_SMEM>>>(Yp, hWo, bo, out);
}